// round 8
// baseline (speedup 1.0000x reference)
#include <cuda_runtime.h>
#include <math.h>

#define Bn   16
#define Cn   256
#define Hn   48
#define Wn   48
#define HWn  2304
#define KK   49

typedef unsigned long long ull;

// f32x2 packed-math macros (sm_103a FFMA2 path)
#define FMA2(d,a,b,c) asm("fma.rn.f32x2 %0, %1, %2, %3;" : "=l"(d) : "l"(a), "l"(b), "l"(c))
#define MUL2(d,a,b)   asm("mul.rn.f32x2 %0, %1, %2;"     : "=l"(d) : "l"(a), "l"(b))
#define PK2(d,lo,hi)  asm("mov.b64 %0, {%1, %2};"        : "=l"(d) : "f"(lo), "f"(hi))
#define UPK2(lo,hi,s) asm("mov.b64 {%0, %1}, %2;"        : "=f"(lo), "=f"(hi) : "l"(s))

// Scratch (device globals, zero-initialized at load; padding rows never written)
__device__ float g_z[Bn * Cn];                               // raw channel sums
__device__ __align__(16) float g_fs[Bn * HWn];
__device__ float g_basis[40 * KK];
__device__ __align__(16) float g_coeffP[3 * Bn * 16 * Cn];   // padded [br,b,16,C]
__device__ float g_G[3 * Bn * 256];                          // padded Gram/C (n*16+m)
__device__ float g_s1[3 * Bn * 16];                          // padded colmean/C
__device__ __align__(16) float g_UP[(size_t)Bn * 3 * 16 * HWn];

// ---------------------------------------------------------------------------
// k_prep: block 0 computes the 40 basis kernels; blocks 1..16 zero g_z
__global__ void k_prep(const float* __restrict__ rw1, const float* __restrict__ rb1,
                       const float* __restrict__ rw2, const float* __restrict__ rb2) {
    int tid = threadIdx.x;
    if (blockIdx.x > 0) {
        int i = (blockIdx.x - 1) * 256 + tid;    // 16*256 = 4096 = Bn*Cn
        g_z[i] = 0.f;
        return;
    }
    __shared__ float r[KK], th[KK];
    if (tid < KK) {
        int i = tid / 7, j = tid % 7;
        float gy = (float)i - 3.f, gx = (float)j - 3.f;
        r[tid] = sqrtf(gx * gx + gy * gy + 1e-8f);
        th[tid] = atan2f(gy, gx);
    }
    __syncthreads();

    if (tid < 24) {
        bool inv = tid < 8;
        int i = inv ? tid : (tid - 8);
        int combo = i % 9;
        int d = combo / 3, si = combo % 3;
        float sig = inv ? (4.f + 2.f * (float)si) : (1.f + (float)si);
        float psi[KK];
        float ss = 0.f;
        for (int c = 0; c < KK; ++c) {
            float u = r[c] / sig;
            float g = expf(-0.5f * u * u);
            float p = (d == 0) ? 1.f : ((d == 1) ? u : (u * u - 1.f));
            psi[c] = p * g;
            ss += psi[c] * psi[c];
        }
        float inorm = 1.f / sqrtf(ss + 1e-8f);
        int gi = inv ? tid : (8 + i);
        for (int c = 0; c < KK; ++c) g_basis[gi * KK + c] = psi[c] * inorm;
    }

    if (tid < KK) {
        float rad0 = rb2[0], rad1 = rb2[1];
        for (int h = 0; h < 32; ++h) {
            float t = tanhf(r[tid] * rw1[h] + rb1[h]);
            rad0 += t * rw2[h * 2 + 0];
            rad1 += t * rw2[h * 2 + 1];
        }
        for (int l = 0; l < 8; ++l) {
            float o = (float)(l / 2 + 1);
            float a = (l & 1) ? sinf(o * th[tid]) : cosf(o * th[tid]);
            g_basis[(24 + l) * KK + tid]     = rad0 * a;
            g_basis[(24 + 8 + l) * KK + tid] = rad1 * a;
        }
    }
}

// ---------------------------------------------------------------------------
// k_reduce v2 (transposed, NO fs atomics): block owns 256 pixels of batch b,
// loops all channels. fs accumulated in a register, stored once. z partials
// via warp shuffle + lane0 atomicAdd into pre-zeroed g_z (raw sums).
// grid (9, B), block 256.
__global__ void k_reduce(const float* __restrict__ feat) {
    int b = blockIdx.y, seg = blockIdx.x;
    int tid = threadIdx.x, lane = tid & 31;
    int p = seg * 256 + tid;
    const float* fb = feat + (size_t)b * Cn * HWn + p;
    float* zb = g_z + b * Cn;
    float fs = 0.f;
#pragma unroll 8
    for (int c = 0; c < Cn; ++c) {
        float v = __ldg(fb + (size_t)c * HWn);
        fs += v;
        float cs = v;
#pragma unroll
        for (int o = 16; o; o >>= 1) cs += __shfl_xor_sync(0xffffffffu, cs, o);
        if (lane == 0) atomicAdd(&zb[c], cs);
    }
    g_fs[b * HWn + p] = fs;
}

// ---------------------------------------------------------------------------
// k_mlp: fused hidden + coeff + stats, templated on N to keep acc[] in regs
template <int N>
__device__ __forceinline__ void mlp_body(
    int br, int b, int tid,
    const float* __restrict__ w1, const float* __restrict__ b1,
    const float* __restrict__ w2, const float* __restrict__ b2,
    float* zz, float (*hp)[64], float* hh, float* sc) {
    const int NC = N * Cn;
    if (tid < Cn) zz[tid] = g_z[b * Cn + tid] * (1.f / (float)HWn);
    __syncthreads();
    if (tid < 256) {
        int j = tid & 63, s = tid >> 6;
        float a = 0.f;
        const float* wp = w1 + (size_t)(64 * s) * 64 + j;
#pragma unroll 8
        for (int c = 0; c < 64; ++c) a += zz[64 * s + c] * wp[c * 64];
        hp[s][j] = a;
    }
    __syncthreads();
    if (tid < 64)
        hh[tid] = fmaxf(hp[0][tid] + hp[1][tid] + hp[2][tid] + hp[3][tid] + b1[tid], 0.f);
    __syncthreads();
    if (tid < Cn) {
        int c = tid;
        float acc[N];
#pragma unroll
        for (int n = 0; n < N; ++n) acc[n] = b2[n * Cn + c];
        for (int h2 = 0; h2 < 64; ++h2) {
            float hv = hh[h2];
            const float* wp = w2 + (size_t)h2 * NC + c;
#pragma unroll
            for (int n = 0; n < N; ++n) acc[n] += hv * wp[n * Cn];
        }
#pragma unroll
        for (int n = 0; n < N; ++n) {
            sc[n * Cn + c] = acc[n];
            g_coeffP[((size_t)(br * Bn + b) * 16 + n) * Cn + c] = acc[n];
        }
    }
    __syncthreads();
    if (tid < N * N) {
        int n = tid / N, m = tid % N;
        float a = 0.f;
#pragma unroll 4
        for (int c = 0; c < Cn; ++c) a += sc[n * Cn + c] * sc[m * Cn + c];
        g_G[(br * Bn + b) * 256 + n * 16 + m] = a * (1.f / (float)Cn);
    } else if (tid < N * N + N) {
        int n = tid - N * N;
        float a = 0.f;
#pragma unroll 4
        for (int c = 0; c < Cn; ++c) a += sc[n * Cn + c];
        g_s1[(br * Bn + b) * 16 + n] = a * (1.f / (float)Cn);
    }
}

__global__ void k_mlp(const float* __restrict__ w1i, const float* __restrict__ b1i,
                      const float* __restrict__ w2i, const float* __restrict__ b2i,
                      const float* __restrict__ w1e, const float* __restrict__ b1e,
                      const float* __restrict__ w2e, const float* __restrict__ b2e,
                      const float* __restrict__ w1c, const float* __restrict__ b1c,
                      const float* __restrict__ w2c, const float* __restrict__ b2c) {
    int br = blockIdx.x, b = blockIdx.y, tid = threadIdx.x;
    __shared__ float zz[Cn];
    __shared__ float hp[4][64];
    __shared__ float hh[64];
    __shared__ float sc[16 * Cn];
    if (br == 0)
        mlp_body<8>(0, b, tid, w1i, b1i, w2i, b2i, zz, hp, hh, sc);
    else if (br == 1)
        mlp_body<16>(1, b, tid, w1e, b1e, w2e, b2e, zz, hp, hh, sc);
    else
        mlp_body<16>(2, b, tid, w1c, b1c, w2c, b2c, zz, hp, hh, sc);
}

// ---------------------------------------------------------------------------
// k_uconv: register-blocked 7x7 conv, 2 bases per block (tile reuse).
// grid (20, B), block 192
__global__ void k_uconv() {
    int pair = blockIdx.x, b = blockIdx.y, tid = threadIdx.x;
    __shared__ float fp[54 * 54];
    __shared__ float bs[2][KK];
    if (tid < 2 * KK) bs[tid / KK][tid % KK] = g_basis[(pair * 2) * KK + tid];
    for (int i = tid; i < 54 * 54; i += 192) {
        int row = i / 54, col = i % 54;
        int y = row - 3, x = col - 3;
        fp[i] = (y >= 0 && y < Hn && x >= 0 && x < Wn) ? g_fs[b * HWn + y * Wn + x] : 0.f;
    }
    __syncthreads();

    int x = tid % 48, yg0 = tid / 48;
#pragma unroll
    for (int gi = 0; gi < 2; ++gi) {
        int g = pair * 2 + gi;
        int br = (g < 8) ? 0 : ((g < 24) ? 1 : 2);
        int nl = g - ((br == 0) ? 0 : ((br == 1) ? 8 : 24));
        float* up = g_UP + (((size_t)b * 3 + br) * 16 + nl) * HWn;
#pragma unroll
        for (int it = 0; it < 3; ++it) {
            int y0 = (yg0 + 4 * it) * 4;
            float a0 = 0.f, a1 = 0.f, a2 = 0.f, a3 = 0.f;
#pragma unroll
            for (int ri = 0; ri < 10; ++ri) {
                float t[7];
#pragma unroll
                for (int dx = 0; dx < 7; ++dx) t[dx] = fp[(y0 + ri) * 54 + x + dx];
#pragma unroll
                for (int o = 0; o < 4; ++o) {
                    int dy = ri - o;
                    if (dy >= 0 && dy < 7) {
                        float s = 0.f;
#pragma unroll
                        for (int dx = 0; dx < 7; ++dx) s += t[dx] * bs[gi][dy * 7 + dx];
                        if (o == 0) a0 += s; else if (o == 1) a1 += s;
                        else if (o == 2) a2 += s; else a3 += s;
                    }
                }
            }
            up[(y0 + 0) * Wn + x] = a0;
            up[(y0 + 1) * Wn + x] = a1;
            up[(y0 + 2) * Wn + x] = a2;
            up[(y0 + 3) * Wn + x] = a3;
        }
    }
}

// ---------------------------------------------------------------------------
// k_main: inline LN stats + f32x2 GEMM + store, 64-channel groups.
// grid (3, B, 12): z = br*4 + cq. block 192, thread owns 4 consecutive pixels.
__global__ void __launch_bounds__(192)
k_main(const float* __restrict__ lig, const float* __restrict__ lib,
       const float* __restrict__ leg, const float* __restrict__ leb,
       const float* __restrict__ lcg, const float* __restrict__ lcb,
       float* __restrict__ out) {
    int chunk = blockIdx.x, b = blockIdx.y;
    int br = blockIdx.z >> 2, cq = blockIdx.z & 3;
    int c0 = cq * 64;
    int tid = threadIdx.x;

    const float* lng = (br == 0) ? lig : ((br == 1) ? leg : lcg);
    const float* lnb = (br == 0) ? lib : ((br == 1) ? leb : lcb);

    __shared__ ull scf2[16 * 64];   // dup-packed coeffs (8 KB)
    __shared__ ull sga[64], sbb[64];
    __shared__ float sG[256];
    __shared__ float sm1[16];

    const float* cf = g_coeffP + (size_t)(br * Bn + b) * 16 * Cn + c0;
    for (int i = tid; i < 16 * 64; i += 192) {
        int n = i >> 6, c = i & 63;
        float w = cf[n * Cn + c];
        ull p; PK2(p, w, w);
        scf2[i] = p;
    }
    if (tid < 64) {
        float A = lng[c0 + tid], Bc = lnb[c0 + tid];
        ull pa, pb; PK2(pa, A, A); PK2(pb, Bc, Bc);
        sga[tid] = pa; sbb[tid] = pb;
    } else if (tid < 80) {
        sm1[tid - 64] = g_s1[(br * Bn + b) * 16 + tid - 64];
    }
    { int i = tid; if (i < 256) {} }
    for (int i = tid; i < 256; i += 192) sG[i] = g_G[(br * Bn + b) * 256 + i];
    __syncthreads();

    int p0 = chunk * 768 + tid * 4;
    const float* ub = g_UP + ((size_t)b * 3 + br) * 16 * HWn;
    ull u[16][2];
#pragma unroll
    for (int n = 0; n < 16; ++n) {
        float4 v4 = *(const float4*)(ub + (size_t)n * HWn + p0);
        PK2(u[n][0], v4.x, v4.y);
        PK2(u[n][1], v4.z, v4.w);
    }

    // LN stats inline: mean and E[x^2] via Gram quadratic form
    ull m0 = 0ull, m1 = 0ull;
#pragma unroll
    for (int n = 0; n < 16; ++n) {
        ull s2; float s = sm1[n]; PK2(s2, s, s);
        FMA2(m0, s2, u[n][0], m0);
        FMA2(m1, s2, u[n][1], m1);
    }
    ull q0 = 0ull, q1 = 0ull;
#pragma unroll
    for (int n = 0; n < 16; ++n) {
        ull t0 = 0ull, t1 = 0ull;
#pragma unroll
        for (int mm = 0; mm < 16; ++mm) {
            ull g2; float gg = sG[n * 16 + mm]; PK2(g2, gg, gg);
            FMA2(t0, g2, u[mm][0], t0);
            FMA2(t1, g2, u[mm][1], t1);
        }
        FMA2(q0, t0, u[n][0], q0);
        FMA2(q1, t1, u[n][1], q1);
    }
    float mx, my, mz, mw, qx, qy, qz, qw;
    UPK2(mx, my, m0); UPK2(mz, mw, m1);
    UPK2(qx, qy, q0); UPK2(qz, qw, q1);
    float rx = rsqrtf(fmaxf(qx - mx * mx, 0.f) + 1e-5f);
    float ry = rsqrtf(fmaxf(qy - my * my, 0.f) + 1e-5f);
    float rz = rsqrtf(fmaxf(qz - mz * mz, 0.f) + 1e-5f);
    float rw = rsqrtf(fmaxf(qw - mw * mw, 0.f) + 1e-5f);
    ull r0, r1, nm0, nm1;
    PK2(r0, rx, ry); PK2(r1, rz, rw);
    PK2(nm0, -mx, -my); PK2(nm1, -mz, -mw);

    float* ob = out + (size_t)br * Bn * Cn * HWn + (size_t)b * Cn * HWn
                    + (size_t)c0 * HWn + p0;
#pragma unroll 4
    for (int c = 0; c < 64; ++c) {
        ull v0 = 0ull, v1 = 0ull;
        const ull* wrow = scf2 + c;
#pragma unroll
        for (int n = 0; n < 16; ++n) {
            ull w = wrow[n * 64];
            FMA2(v0, w, u[n][0], v0);
            FMA2(v1, w, u[n][1], v1);
        }
        ull A2 = sga[c], B2 = sbb[c];
        ull rA0, rA1, bias0, bias1, o0, o1;
        MUL2(rA0, r0, A2);
        MUL2(rA1, r1, A2);
        FMA2(bias0, nm0, rA0, B2);
        FMA2(bias1, nm1, rA1, B2);
        FMA2(o0, v0, rA0, bias0);
        FMA2(o1, v1, rA1, bias1);
        float4 o;
        UPK2(o.x, o.y, o0);
        UPK2(o.z, o.w, o1);
        *(float4*)(ob + (size_t)c * HWn) = o;
    }
}

// ---------------------------------------------------------------------------
extern "C" void kernel_launch(void* const* d_in, const int* in_sizes, int n_in,
                              void* d_out, int out_size) {
    const float* feat = (const float*)d_in[0];
    const float* iw1 = (const float*)d_in[1];
    const float* ib1 = (const float*)d_in[2];
    const float* iw2 = (const float*)d_in[3];
    const float* ib2 = (const float*)d_in[4];
    const float* ew1 = (const float*)d_in[5];
    const float* eb1 = (const float*)d_in[6];
    const float* ew2 = (const float*)d_in[7];
    const float* eb2 = (const float*)d_in[8];
    const float* cw1 = (const float*)d_in[9];
    const float* cb1 = (const float*)d_in[10];
    const float* cw2 = (const float*)d_in[11];
    const float* cb2 = (const float*)d_in[12];
    const float* rw1 = (const float*)d_in[13];
    const float* rb1 = (const float*)d_in[14];
    const float* rw2 = (const float*)d_in[15];
    const float* rb2 = (const float*)d_in[16];
    const float* lig = (const float*)d_in[17];
    const float* lib = (const float*)d_in[18];
    const float* leg = (const float*)d_in[19];
    const float* leb = (const float*)d_in[20];
    const float* lcg = (const float*)d_in[21];
    const float* lcb = (const float*)d_in[22];
    float* out = (float*)d_out;

    k_prep<<<17, 256>>>(rw1, rb1, rw2, rb2);
    k_reduce<<<dim3(9, Bn), 256>>>(feat);
    k_mlp<<<dim3(3, Bn), 288>>>(iw1, ib1, iw2, ib2, ew1, eb1, ew2, eb2, cw1, cb1, cw2, cb2);
    k_uconv<<<dim3(20, Bn), 192>>>();
    k_main<<<dim3(3, Bn, 12), 192>>>(lig, lib, leg, leb, lcg, lcb, out);
}

// round 9
// speedup vs baseline: 1.1414x; 1.1414x over previous
#include <cuda_runtime.h>
#include <math.h>

#define Bn   16
#define Cn   256
#define Hn   48
#define Wn   48
#define HWn  2304
#define NG   40
#define KK   49

// Scratch (device globals: allocation-free rule)
__device__ float g_z[Bn * Cn];                 // GAP [B, C]
__device__ float g_fs[Bn * HWn];               // channel sum [B, H, W]
__device__ float g_basis[NG * KK];             // bases
__device__ float g_coeff[Bn * NG * Cn];        // coeffs [B, nG, C]
__device__ float g_G[3 * Bn * 256];            // Gram/C (n*N+m layout)
__device__ float g_s1[3 * Bn * 16];            // colmean/C
__device__ float g_U[(size_t)Bn * NG * HWn];   // basis convs [B, nG, HW]

// ---------------------------------------------------------------------------
// k_prep: block 0 computes the 40 basis kernels; blocks 1..144 zero g_fs
__global__ void k_prep(const float* __restrict__ rw1, const float* __restrict__ rb1,
                       const float* __restrict__ rw2, const float* __restrict__ rb2) {
    int tid = threadIdx.x;
    if (blockIdx.x > 0) {
        int i = (blockIdx.x - 1) * 256 + tid;   // 144*256 = 36864 = Bn*HWn
        g_fs[i] = 0.f;
        return;
    }
    __shared__ float r[KK], th[KK];
    if (tid < KK) {
        int i = tid / 7, j = tid % 7;
        float gy = (float)i - 3.f, gx = (float)j - 3.f;
        r[tid] = sqrtf(gx * gx + gy * gy + 1e-8f);
        th[tid] = atan2f(gy, gx);
    }
    __syncthreads();

    // Gaussian bases: inv (tid 0..7), eq (tid 8..23)
    if (tid < 24) {
        bool inv = tid < 8;
        int i = inv ? tid : (tid - 8);
        int combo = i % 9;
        int d = combo / 3, si = combo % 3;
        float sig = inv ? (4.f + 2.f * (float)si) : (1.f + (float)si);
        float psi[KK];
        float ss = 0.f;
        for (int c = 0; c < KK; ++c) {
            float u = r[c] / sig;
            float g = expf(-0.5f * u * u);
            float p = (d == 0) ? 1.f : ((d == 1) ? u : (u * u - 1.f));
            psi[c] = p * g;
            ss += psi[c] * psi[c];
        }
        float inorm = 1.f / sqrtf(ss + 1e-8f);
        int gi = inv ? tid : (8 + i);
        for (int c = 0; c < KK; ++c) g_basis[gi * KK + c] = psi[c] * inorm;
    }

    // Harmonic bases: one thread per cell
    if (tid < KK) {
        float rad0 = rb2[0], rad1 = rb2[1];
        for (int h = 0; h < 32; ++h) {
            float t = tanhf(r[tid] * rw1[h] + rb1[h]);
            rad0 += t * rw2[h * 2 + 0];
            rad1 += t * rw2[h * 2 + 1];
        }
        for (int l = 0; l < 8; ++l) {
            float o = (float)(l / 2 + 1);
            float a = (l & 1) ? sinf(o * th[tid]) : cosf(o * th[tid]);
            g_basis[(24 + l) * KK + tid]     = rad0 * a;
            g_basis[(24 + 8 + l) * KK + tid] = rad1 * a;
        }
    }
}

// ---------------------------------------------------------------------------
// k_reduce: z[b,c] = mean_HW(feature), fs[b,p] = sum_C(feature)
// grid (16 chunks of 16 channels, B), block 256   [round-0 champion verbatim]
__global__ void k_reduce(const float* __restrict__ feat) {
    int b = blockIdx.y, chunk = blockIdx.x;
    int tid = threadIdx.x;
    int lane = tid & 31, wid = tid >> 5;
    __shared__ float zsum[16][8];

    float facc[9];
#pragma unroll
    for (int k = 0; k < 9; ++k) facc[k] = 0.f;

    const float* fb = feat + ((size_t)b * Cn + (size_t)chunk * 16) * HWn;
    for (int c = 0; c < 16; ++c) {
        const float* fp = fb + (size_t)c * HWn;
        float csum = 0.f;
#pragma unroll
        for (int k = 0; k < 9; ++k) {
            float v = fp[tid + 256 * k];
            facc[k] += v;
            csum += v;
        }
#pragma unroll
        for (int o = 16; o; o >>= 1) csum += __shfl_xor_sync(0xffffffffu, csum, o);
        if (lane == 0) zsum[c][wid] = csum;
    }
    __syncthreads();
    if (tid < 16) {
        float s = 0.f;
#pragma unroll
        for (int w = 0; w < 8; ++w) s += zsum[tid][w];
        g_z[b * Cn + chunk * 16 + tid] = s * (1.f / (float)HWn);
    }
#pragma unroll
    for (int k = 0; k < 9; ++k)
        atomicAdd(&g_fs[b * HWn + tid + 256 * k], facc[k]);
}

// ---------------------------------------------------------------------------
// k_mlp: fused hidden + coeff + stats per (branch, b). grid (3, B), block 288.
// Writes round-0 layouts: g_coeff [B,40,C], g_G n*N+m stride, g_s1.
template <int N>
__device__ __forceinline__ void mlp_body(
    int br, int nbase, int b, int tid,
    const float* __restrict__ w1, const float* __restrict__ b1,
    const float* __restrict__ w2, const float* __restrict__ b2,
    float* zz, float (*hp)[64], float* hh, float* sc) {
    const int NC = N * Cn;
    if (tid < Cn) zz[tid] = g_z[b * Cn + tid];
    __syncthreads();
    if (tid < 256) {
        int j = tid & 63, s = tid >> 6;
        float a = 0.f;
        const float* wp = w1 + (size_t)(64 * s) * 64 + j;
#pragma unroll 8
        for (int c = 0; c < 64; ++c) a += zz[64 * s + c] * wp[c * 64];
        hp[s][j] = a;
    }
    __syncthreads();
    if (tid < 64)
        hh[tid] = fmaxf(hp[0][tid] + hp[1][tid] + hp[2][tid] + hp[3][tid] + b1[tid], 0.f);
    __syncthreads();
    if (tid < Cn) {
        int c = tid;
        float acc[N];
#pragma unroll
        for (int n = 0; n < N; ++n) acc[n] = b2[n * Cn + c];
        for (int h2 = 0; h2 < 64; ++h2) {
            float hv = hh[h2];
            const float* wp = w2 + (size_t)h2 * NC + c;
#pragma unroll
            for (int n = 0; n < N; ++n) acc[n] += hv * wp[n * Cn];
        }
#pragma unroll
        for (int n = 0; n < N; ++n) {
            sc[n * Cn + c] = acc[n];
            g_coeff[((size_t)b * NG + nbase + n) * Cn + c] = acc[n];
        }
    }
    __syncthreads();
    if (tid < N * N) {
        int n = tid / N, m = tid % N;
        float a = 0.f;
#pragma unroll 4
        for (int c = 0; c < Cn; ++c) a += sc[n * Cn + c] * sc[m * Cn + c];
        g_G[(br * Bn + b) * 256 + tid] = a * (1.f / (float)Cn);   // n*N+m layout
    } else if (tid < N * N + N) {
        int n = tid - N * N;
        float a = 0.f;
#pragma unroll 4
        for (int c = 0; c < Cn; ++c) a += sc[n * Cn + c];
        g_s1[(br * Bn + b) * 16 + n] = a * (1.f / (float)Cn);
    }
}

__global__ void k_mlp(const float* __restrict__ w1i, const float* __restrict__ b1i,
                      const float* __restrict__ w2i, const float* __restrict__ b2i,
                      const float* __restrict__ w1e, const float* __restrict__ b1e,
                      const float* __restrict__ w2e, const float* __restrict__ b2e,
                      const float* __restrict__ w1c, const float* __restrict__ b1c,
                      const float* __restrict__ w2c, const float* __restrict__ b2c) {
    int br = blockIdx.x, b = blockIdx.y, tid = threadIdx.x;
    __shared__ float zz[Cn];
    __shared__ float hp[4][64];
    __shared__ float hh[64];
    __shared__ float sc[16 * Cn];
    if (br == 0)
        mlp_body<8>(0, 0, b, tid, w1i, b1i, w2i, b2i, zz, hp, hh, sc);
    else if (br == 1)
        mlp_body<16>(1, 8, b, tid, w1e, b1e, w2e, b2e, zz, hp, hh, sc);
    else
        mlp_body<16>(2, 24, b, tid, w1c, b1c, w2c, b2c, zz, hp, hh, sc);
}

// ---------------------------------------------------------------------------
// k_uconv: register-blocked 7x7 conv (round-7 measured 15.0us, regs 36).
// grid (40, B), block 192. Writes g_U [B, 40, HW].
__global__ void k_uconv() {
    int g = blockIdx.x, b = blockIdx.y, tid = threadIdx.x;
    __shared__ float fp[54 * 54];
    __shared__ float bs[KK];
    if (tid < KK) bs[tid] = g_basis[g * KK + tid];
    for (int i = tid; i < 54 * 54; i += 192) {
        int row = i / 54, col = i % 54;
        int y = row - 3, x = col - 3;
        fp[i] = (y >= 0 && y < Hn && x >= 0 && x < Wn) ? g_fs[b * HWn + y * Wn + x] : 0.f;
    }
    __syncthreads();

    int x = tid % 48, yg0 = tid / 48;   // yg0 in 0..3
    float* up = g_U + ((size_t)b * NG + g) * HWn;
#pragma unroll
    for (int it = 0; it < 3; ++it) {
        int y0 = (yg0 + 4 * it) * 4;    // 4 vertically adjacent outputs
        float a0 = 0.f, a1 = 0.f, a2 = 0.f, a3 = 0.f;
#pragma unroll
        for (int ri = 0; ri < 10; ++ri) {
            float t[7];
#pragma unroll
            for (int dx = 0; dx < 7; ++dx) t[dx] = fp[(y0 + ri) * 54 + x + dx];
#pragma unroll
            for (int o = 0; o < 4; ++o) {
                int dy = ri - o;
                if (dy >= 0 && dy < 7) {
                    float s = 0.f;
#pragma unroll
                    for (int dx = 0; dx < 7; ++dx) s += t[dx] * bs[dy * 7 + dx];
                    if (o == 0) a0 += s; else if (o == 1) a1 += s;
                    else if (o == 2) a2 += s; else a3 += s;
                }
            }
        }
        up[(y0 + 0) * Wn + x] = a0;
        up[(y0 + 1) * Wn + x] = a1;
        up[(y0 + 2) * Wn + x] = a2;
        up[(y0 + 3) * Wn + x] = a3;
    }
}

// ---------------------------------------------------------------------------
// k_main: round-0 champion body, merged into ONE launch, grid (3, B, 3).
// Each thread owns 3 pixels (p0, p0+256, p0+512). Inline LN stats.
template <int N>
__device__ __forceinline__ void main_body(
    int br, int nbase, int b, int chunk, int tid,
    const float* __restrict__ lng, const float* __restrict__ lnb,
    float* __restrict__ out,
    float* sc, float* sg, float* sb, float* sG, float* sm) {
    const float* cf = g_coeff + ((size_t)b * NG + nbase) * Cn;
    for (int i = tid; i < N * Cn; i += 256) sc[i] = cf[i];
    sg[tid] = lng[tid];
    sb[tid] = lnb[tid];
    if (tid < N * N) sG[tid] = g_G[(br * Bn + b) * 256 + tid];
    if (tid < N) sm[tid] = g_s1[(br * Bn + b) * 16 + tid];
    __syncthreads();

    int p0 = chunk * 768 + tid;
    const float* up = g_U + ((size_t)b * NG + nbase) * HWn;
    float u0[N], u1[N], u2[N];
#pragma unroll
    for (int n = 0; n < N; ++n) {
        u0[n] = up[n * HWn + p0];
        u1[n] = up[n * HWn + p0 + 256];
        u2[n] = up[n * HWn + p0 + 512];
    }
    // channel mean per pixel
    float m0 = 0.f, m1 = 0.f, m2 = 0.f;
#pragma unroll
    for (int n = 0; n < N; ++n) {
        float s = sm[n];
        m0 += s * u0[n]; m1 += s * u1[n]; m2 += s * u2[n];
    }
    // E[x^2] per pixel via Gram quadratic form
    float q0 = 0.f, q1 = 0.f, q2 = 0.f;
#pragma unroll
    for (int n = 0; n < N; ++n) {
        float t0 = 0.f, t1 = 0.f, t2 = 0.f;
#pragma unroll
        for (int m = 0; m < N; ++m) {
            float gg = sG[n * N + m];
            t0 += gg * u0[m]; t1 += gg * u1[m]; t2 += gg * u2[m];
        }
        q0 += t0 * u0[n]; q1 += t1 * u1[n]; q2 += t2 * u2[n];
    }
    float r0 = rsqrtf(fmaxf(q0 - m0 * m0, 0.f) + 1e-5f);
    float r1 = rsqrtf(fmaxf(q1 - m1 * m1, 0.f) + 1e-5f);
    float r2 = rsqrtf(fmaxf(q2 - m2 * m2, 0.f) + 1e-5f);

    float* ob = out + (size_t)b * Cn * HWn + p0;
    for (int c = 0; c < Cn; ++c) {
        float v0 = 0.f, v1 = 0.f, v2 = 0.f;
#pragma unroll
        for (int n = 0; n < N; ++n) {
            float w = sc[n * Cn + c];
            v0 += w * u0[n]; v1 += w * u1[n]; v2 += w * u2[n];
        }
        float A = sg[c], Bc = sb[c];
        float* o = ob + (size_t)c * HWn;
        o[0]   = (v0 - m0) * r0 * A + Bc;
        o[256] = (v1 - m1) * r1 * A + Bc;
        o[512] = (v2 - m2) * r2 * A + Bc;
    }
}

__global__ void __launch_bounds__(256)
k_main(const float* __restrict__ lig, const float* __restrict__ lib,
       const float* __restrict__ leg, const float* __restrict__ leb,
       const float* __restrict__ lcg, const float* __restrict__ lcb,
       float* __restrict__ out) {
    int chunk = blockIdx.x, b = blockIdx.y, br = blockIdx.z;
    int tid = threadIdx.x;
    __shared__ float sc[16 * Cn];
    __shared__ float sg[Cn], sb[Cn];
    __shared__ float sG[256];
    __shared__ float sm[16];
    const size_t BR = (size_t)Bn * Cn * HWn;
    if (br == 0)
        main_body<8>(0, 0, b, chunk, tid, lig, lib, out, sc, sg, sb, sG, sm);
    else if (br == 1)
        main_body<16>(1, 8, b, chunk, tid, leg, leb, out + BR, sc, sg, sb, sG, sm);
    else
        main_body<16>(2, 24, b, chunk, tid, lcg, lcb, out + 2 * BR, sc, sg, sb, sG, sm);
}

// ---------------------------------------------------------------------------
extern "C" void kernel_launch(void* const* d_in, const int* in_sizes, int n_in,
                              void* d_out, int out_size) {
    const float* feat = (const float*)d_in[0];
    const float* iw1 = (const float*)d_in[1];
    const float* ib1 = (const float*)d_in[2];
    const float* iw2 = (const float*)d_in[3];
    const float* ib2 = (const float*)d_in[4];
    const float* ew1 = (const float*)d_in[5];
    const float* eb1 = (const float*)d_in[6];
    const float* ew2 = (const float*)d_in[7];
    const float* eb2 = (const float*)d_in[8];
    const float* cw1 = (const float*)d_in[9];
    const float* cb1 = (const float*)d_in[10];
    const float* cw2 = (const float*)d_in[11];
    const float* cb2 = (const float*)d_in[12];
    const float* rw1 = (const float*)d_in[13];
    const float* rb1 = (const float*)d_in[14];
    const float* rw2 = (const float*)d_in[15];
    const float* rb2 = (const float*)d_in[16];
    const float* lig = (const float*)d_in[17];
    const float* lib = (const float*)d_in[18];
    const float* leg = (const float*)d_in[19];
    const float* leb = (const float*)d_in[20];
    const float* lcg = (const float*)d_in[21];
    const float* lcb = (const float*)d_in[22];
    float* out = (float*)d_out;

    k_prep<<<145, 256>>>(rw1, rb1, rw2, rb2);
    k_reduce<<<dim3(16, Bn), 256>>>(feat);
    k_mlp<<<dim3(3, Bn), 288>>>(iw1, ib1, iw2, ib2, ew1, eb1, ew2, eb2, cw1, cb1, cw2, cb2);
    k_uconv<<<dim3(40, Bn), 192>>>();
    k_main<<<dim3(3, Bn, 3), 256>>>(lig, lib, leg, leb, lcg, lcb, out);
}

// round 10
// speedup vs baseline: 1.9140x; 1.6769x over previous
#include <cuda_runtime.h>
#include <math.h>

#define Bn   16
#define Cn   256
#define Hn   48
#define Wn   48
#define HWn  2304
#define NG   40
#define KK   49

typedef unsigned long long ull;

// f32x2 packed-math macros (sm_103a FFMA2 path)
#define FMA2(d,a,b,c) asm("fma.rn.f32x2 %0, %1, %2, %3;" : "=l"(d) : "l"(a), "l"(b), "l"(c))
#define MUL2(d,a,b)   asm("mul.rn.f32x2 %0, %1, %2;"     : "=l"(d) : "l"(a), "l"(b))
#define PK2(d,lo,hi)  asm("mov.b64 %0, {%1, %2};"        : "=l"(d) : "f"(lo), "f"(hi))
#define UPK2(lo,hi,s) asm("mov.b64 {%0, %1}, %2;"        : "=f"(lo), "=f"(hi) : "l"(s))

// Scratch (device globals, zero-initialized at load; padding never written)
__device__ float g_z[Bn * Cn];                                  // GAP [B,C]
__device__ float g_fs[Bn * HWn];                                // channel sum
__device__ float g_basis[NG * KK];                              // bases
__device__ __align__(16) float g_coeffT[3 * Bn * Cn * 16];      // [br,b,c,16n] padded
__device__ float g_G[3 * Bn * 256];                             // Gram/C, n*16+m padded
__device__ float g_s1[3 * Bn * 16];                             // colmean/C padded
__device__ __align__(16) float g_UP[(size_t)Bn * 3 * 16 * HWn]; // [b,br,16n,HW] padded

// ---------------------------------------------------------------------------
// k_prep: block 0 computes the 40 basis kernels; blocks 1..144 zero g_fs
__global__ void k_prep(const float* __restrict__ rw1, const float* __restrict__ rb1,
                       const float* __restrict__ rw2, const float* __restrict__ rb2) {
    int tid = threadIdx.x;
    if (blockIdx.x > 0) {
        int i = (blockIdx.x - 1) * 256 + tid;   // 144*256 = Bn*HWn
        g_fs[i] = 0.f;
        return;
    }
    __shared__ float r[KK], th[KK];
    if (tid < KK) {
        int i = tid / 7, j = tid % 7;
        float gy = (float)i - 3.f, gx = (float)j - 3.f;
        r[tid] = sqrtf(gx * gx + gy * gy + 1e-8f);
        th[tid] = atan2f(gy, gx);
    }
    __syncthreads();

    if (tid < 24) {
        bool inv = tid < 8;
        int i = inv ? tid : (tid - 8);
        int combo = i % 9;
        int d = combo / 3, si = combo % 3;
        float sig = inv ? (4.f + 2.f * (float)si) : (1.f + (float)si);
        float psi[KK];
        float ss = 0.f;
        for (int c = 0; c < KK; ++c) {
            float u = r[c] / sig;
            float g = expf(-0.5f * u * u);
            float p = (d == 0) ? 1.f : ((d == 1) ? u : (u * u - 1.f));
            psi[c] = p * g;
            ss += psi[c] * psi[c];
        }
        float inorm = 1.f / sqrtf(ss + 1e-8f);
        int gi = inv ? tid : (8 + i);
        for (int c = 0; c < KK; ++c) g_basis[gi * KK + c] = psi[c] * inorm;
    }

    if (tid < KK) {
        float rad0 = rb2[0], rad1 = rb2[1];
        for (int h = 0; h < 32; ++h) {
            float t = tanhf(r[tid] * rw1[h] + rb1[h]);
            rad0 += t * rw2[h * 2 + 0];
            rad1 += t * rw2[h * 2 + 1];
        }
        for (int l = 0; l < 8; ++l) {
            float o = (float)(l / 2 + 1);
            float a = (l & 1) ? sinf(o * th[tid]) : cosf(o * th[tid]);
            g_basis[(24 + l) * KK + tid]     = rad0 * a;
            g_basis[(24 + 8 + l) * KK + tid] = rad1 * a;
        }
    }
}

// ---------------------------------------------------------------------------
// k_reduce: round-0 champion verbatim. grid (16, B), block 256.
__global__ void k_reduce(const float* __restrict__ feat) {
    int b = blockIdx.y, chunk = blockIdx.x;
    int tid = threadIdx.x;
    int lane = tid & 31, wid = tid >> 5;
    __shared__ float zsum[16][8];

    float facc[9];
#pragma unroll
    for (int k = 0; k < 9; ++k) facc[k] = 0.f;

    const float* fb = feat + ((size_t)b * Cn + (size_t)chunk * 16) * HWn;
    for (int c = 0; c < 16; ++c) {
        const float* fp = fb + (size_t)c * HWn;
        float csum = 0.f;
#pragma unroll
        for (int k = 0; k < 9; ++k) {
            float v = fp[tid + 256 * k];
            facc[k] += v;
            csum += v;
        }
#pragma unroll
        for (int o = 16; o; o >>= 1) csum += __shfl_xor_sync(0xffffffffu, csum, o);
        if (lane == 0) zsum[c][wid] = csum;
    }
    __syncthreads();
    if (tid < 16) {
        float s = 0.f;
#pragma unroll
        for (int w = 0; w < 8; ++w) s += zsum[tid][w];
        g_z[b * Cn + chunk * 16 + tid] = s * (1.f / (float)HWn);
    }
#pragma unroll
    for (int k = 0; k < 9; ++k)
        atomicAdd(&g_fs[b * HWn + tid + 256 * k], facc[k]);
}

// ---------------------------------------------------------------------------
// k_mix: blockIdx-split fused kernel. Blocks 0..47 run the MLP (br,b);
// blocks 48..687 run uconv (g,b). Block 288 threads. Shared smem buffer.
#define SBUF_FLOATS 4672

template <int N>
__device__ __forceinline__ void mlp_body(
    int br, int b, int tid,
    const float* __restrict__ w1, const float* __restrict__ b1,
    const float* __restrict__ w2, const float* __restrict__ b2,
    float* sbuf) {
    float* zz = sbuf;            // 256
    float* hp = sbuf + 256;      // 4*64
    float* hh = sbuf + 512;      // 64
    float* sc = sbuf + 576;      // 16*256
    const int NC = N * Cn;
    if (tid < Cn) zz[tid] = g_z[b * Cn + tid];
    __syncthreads();
    if (tid < 256) {
        int j = tid & 63, s = tid >> 6;
        float a = 0.f;
        const float* wp = w1 + (size_t)(64 * s) * 64 + j;
#pragma unroll 8
        for (int c = 0; c < 64; ++c) a += zz[64 * s + c] * wp[c * 64];
        hp[s * 64 + j] = a;
    }
    __syncthreads();
    if (tid < 64)
        hh[tid] = fmaxf(hp[tid] + hp[64 + tid] + hp[128 + tid] + hp[192 + tid] + b1[tid], 0.f);
    __syncthreads();
    if (tid < Cn) {
        int c = tid;
        float acc[N];
#pragma unroll
        for (int n = 0; n < N; ++n) acc[n] = b2[n * Cn + c];
        for (int h2 = 0; h2 < 64; ++h2) {
            float hv = hh[h2];
            const float* wp = w2 + (size_t)h2 * NC + c;
#pragma unroll
            for (int n = 0; n < N; ++n) acc[n] += hv * wp[n * Cn];
        }
#pragma unroll
        for (int n = 0; n < N; ++n) sc[n * Cn + c] = acc[n];
        // transposed, padded coeff store: [c][16] (pad stays zero)
        float4* dst = (float4*)(g_coeffT + ((size_t)(br * Bn + b) * Cn + c) * 16);
#pragma unroll
        for (int k = 0; k < N / 4; ++k)
            dst[k] = make_float4(acc[4 * k], acc[4 * k + 1], acc[4 * k + 2], acc[4 * k + 3]);
    }
    __syncthreads();
    if (tid < N * N) {
        int n = tid / N, m = tid % N;
        float a = 0.f;
#pragma unroll 4
        for (int c = 0; c < Cn; ++c) a += sc[n * Cn + c] * sc[m * Cn + c];
        g_G[(br * Bn + b) * 256 + n * 16 + m] = a * (1.f / (float)Cn);  // n*16+m padded
    } else if (tid < N * N + N) {
        int n = tid - N * N;
        float a = 0.f;
#pragma unroll 4
        for (int c = 0; c < Cn; ++c) a += sc[n * Cn + c];
        g_s1[(br * Bn + b) * 16 + n] = a * (1.f / (float)Cn);
    }
}

__global__ void __launch_bounds__(288)
k_mix(const float* __restrict__ w1i, const float* __restrict__ b1i,
      const float* __restrict__ w2i, const float* __restrict__ b2i,
      const float* __restrict__ w1e, const float* __restrict__ b1e,
      const float* __restrict__ w2e, const float* __restrict__ b2e,
      const float* __restrict__ w1c, const float* __restrict__ b1c,
      const float* __restrict__ w2c, const float* __restrict__ b2c) {
    __shared__ float sbuf[SBUF_FLOATS];
    int bx = blockIdx.x, tid = threadIdx.x;

    if (bx < 48) {
        int br = bx / 16, b = bx % 16;
        if (br == 0)      mlp_body<8>(0, b, tid, w1i, b1i, w2i, b2i, sbuf);
        else if (br == 1) mlp_body<16>(1, b, tid, w1e, b1e, w2e, b2e, sbuf);
        else              mlp_body<16>(2, b, tid, w1c, b1c, w2c, b2c, sbuf);
        return;
    }

    // ---- uconv role ----
    int gb = bx - 48;
    int g = gb % NG, b = gb / NG;
    int br = (g < 8) ? 0 : ((g < 24) ? 1 : 2);
    int nl = g - ((br == 0) ? 0 : ((br == 1) ? 8 : 24));
    float* fp = sbuf;            // 54*54 = 2916
    float* bs = sbuf + 2916;     // 49
    if (tid < KK) bs[tid] = g_basis[g * KK + tid];
    for (int i = tid; i < 54 * 54; i += 288) {
        int row = i / 54, col = i % 54;
        int y = row - 3, x = col - 3;
        fp[i] = (y >= 0 && y < Hn && x >= 0 && x < Wn) ? g_fs[b * HWn + y * Wn + x] : 0.f;
    }
    __syncthreads();

    int x = tid % 48, yg0 = tid / 48;   // yg0 in 0..5
    float* up = g_UP + (((size_t)b * 3 + br) * 16 + nl) * HWn;
#pragma unroll
    for (int it = 0; it < 2; ++it) {
        int y0 = (yg0 + 6 * it) * 4;    // 4 vertically adjacent outputs
        float a0 = 0.f, a1 = 0.f, a2 = 0.f, a3 = 0.f;
#pragma unroll
        for (int ri = 0; ri < 10; ++ri) {
            float t[7];
#pragma unroll
            for (int dx = 0; dx < 7; ++dx) t[dx] = fp[(y0 + ri) * 54 + x + dx];
#pragma unroll
            for (int o = 0; o < 4; ++o) {
                int dy = ri - o;
                if (dy >= 0 && dy < 7) {
                    float s = 0.f;
#pragma unroll
                    for (int dx = 0; dx < 7; ++dx) s += t[dx] * bs[dy * 7 + dx];
                    if (o == 0) a0 += s; else if (o == 1) a1 += s;
                    else if (o == 2) a2 += s; else a3 += s;
                }
            }
        }
        up[(y0 + 0) * Wn + x] = a0;
        up[(y0 + 1) * Wn + x] = a1;
        up[(y0 + 2) * Wn + x] = a2;
        up[(y0 + 3) * Wn + x] = a3;
    }
}

// ---------------------------------------------------------------------------
// k_main: uniform N=16 (zero padding), dup-packed smem, FFMA2 everywhere.
// grid (3, B, 3), block 384, 2 consecutive pixels per thread.
__global__ void __launch_bounds__(384)
k_main(const float* __restrict__ lig, const float* __restrict__ lib,
       const float* __restrict__ leg, const float* __restrict__ leb,
       const float* __restrict__ lcg, const float* __restrict__ lcb,
       float* __restrict__ out) {
    int chunk = blockIdx.x, b = blockIdx.y, br = blockIdx.z;
    int tid = threadIdx.x;

    const float* lng = (br == 0) ? lig : ((br == 1) ? leg : lcg);
    const float* lnb = (br == 0) ? lib : ((br == 1) ? leb : lcb);

    __shared__ ull s_cf[256 * 16];       // dup-packed coeffs [c][n]  (32 KB)
    __shared__ ulonglong2 s_gb[256];     // (gamma2, beta2)           (4 KB)
    __shared__ ull s_G[256];             // dup-packed Gram           (2 KB)
    __shared__ ull s_m1[16];

    const float4* cf4 = (const float4*)(g_coeffT + (size_t)(br * Bn + b) * Cn * 16);
    for (int i = tid; i < 1024; i += 384) {
        float4 v = cf4[i];
        ull p0, p1, p2, p3;
        PK2(p0, v.x, v.x); PK2(p1, v.y, v.y); PK2(p2, v.z, v.z); PK2(p3, v.w, v.w);
        s_cf[4 * i + 0] = p0; s_cf[4 * i + 1] = p1;
        s_cf[4 * i + 2] = p2; s_cf[4 * i + 3] = p3;
    }
    for (int i = tid; i < 256; i += 384) {
        float A = lng[i], Bc = lnb[i];
        ull a2, b2; PK2(a2, A, A); PK2(b2, Bc, Bc);
        s_gb[i] = make_ulonglong2(a2, b2);
        float gg = g_G[(br * Bn + b) * 256 + i];
        ull g2; PK2(g2, gg, gg);
        s_G[i] = g2;
    }
    if (tid < 16) {
        float s = g_s1[(br * Bn + b) * 16 + tid];
        ull s2; PK2(s2, s, s);
        s_m1[tid] = s2;
    }
    __syncthreads();

    int p0 = chunk * 768 + tid * 2;
    const float* ub = g_UP + ((size_t)b * 3 + br) * 16 * HWn;
    ull u[16];
#pragma unroll
    for (int n = 0; n < 16; ++n) {
        float2 v = *(const float2*)(ub + (size_t)n * HWn + p0);
        PK2(u[n], v.x, v.y);
    }

    // LN stats: mean + E[x^2] via Gram quadratic form (padding rows are zero)
    ull m = 0ull, q = 0ull;
#pragma unroll
    for (int n = 0; n < 16; ++n) FMA2(m, s_m1[n], u[n], m);
#pragma unroll
    for (int n = 0; n < 16; ++n) {
        ull t = 0ull;
#pragma unroll
        for (int mm = 0; mm < 16; ++mm) FMA2(t, s_G[n * 16 + mm], u[mm], t);
        FMA2(q, t, u[n], q);
    }
    float mx, my, qx, qy;
    UPK2(mx, my, m); UPK2(qx, qy, q);
    float rx = rsqrtf(fmaxf(qx - mx * mx, 0.f) + 1e-5f);
    float ry = rsqrtf(fmaxf(qy - my * my, 0.f) + 1e-5f);
    ull r2, nm;
    PK2(r2, rx, ry);
    PK2(nm, -mx, -my);

    float* ob = out + (size_t)br * Bn * Cn * HWn + (size_t)b * Cn * HWn + p0;
#pragma unroll 4
    for (int c = 0; c < 256; ++c) {
        ull v = 0ull;
        const ulonglong2* w2 = (const ulonglong2*)(s_cf + c * 16);
#pragma unroll
        for (int k = 0; k < 8; ++k) {
            ulonglong2 ww = w2[k];
            FMA2(v, ww.x, u[2 * k + 0], v);
            FMA2(v, ww.y, u[2 * k + 1], v);
        }
        ulonglong2 gb = s_gb[c];
        ull rA, bias, o;
        MUL2(rA, r2, gb.x);
        FMA2(bias, nm, rA, gb.y);
        FMA2(o, v, rA, bias);
        *(ull*)(ob + (size_t)c * HWn) = o;
    }
}

// ---------------------------------------------------------------------------
extern "C" void kernel_launch(void* const* d_in, const int* in_sizes, int n_in,
                              void* d_out, int out_size) {
    const float* feat = (const float*)d_in[0];
    const float* iw1 = (const float*)d_in[1];
    const float* ib1 = (const float*)d_in[2];
    const float* iw2 = (const float*)d_in[3];
    const float* ib2 = (const float*)d_in[4];
    const float* ew1 = (const float*)d_in[5];
    const float* eb1 = (const float*)d_in[6];
    const float* ew2 = (const float*)d_in[7];
    const float* eb2 = (const float*)d_in[8];
    const float* cw1 = (const float*)d_in[9];
    const float* cb1 = (const float*)d_in[10];
    const float* cw2 = (const float*)d_in[11];
    const float* cb2 = (const float*)d_in[12];
    const float* rw1 = (const float*)d_in[13];
    const float* rb1 = (const float*)d_in[14];
    const float* rw2 = (const float*)d_in[15];
    const float* rb2 = (const float*)d_in[16];
    const float* lig = (const float*)d_in[17];
    const float* lib = (const float*)d_in[18];
    const float* leg = (const float*)d_in[19];
    const float* leb = (const float*)d_in[20];
    const float* lcg = (const float*)d_in[21];
    const float* lcb = (const float*)d_in[22];
    float* out = (float*)d_out;

    k_prep<<<145, 256>>>(rw1, rb1, rw2, rb2);
    k_reduce<<<dim3(16, Bn), 256>>>(feat);
    k_mix<<<688, 288>>>(iw1, ib1, iw2, ib2, ew1, eb1, ew2, eb2, cw1, cb1, cw2, cb2);
    k_main<<<dim3(3, Bn, 3), 384>>>(lig, lib, leg, leb, lcg, lcb, out);
}

// round 11
// speedup vs baseline: 2.0092x; 1.0497x over previous
#include <cuda_runtime.h>
#include <math.h>

#define Bn   16
#define Cn   256
#define Hn   48
#define Wn   48
#define HWn  2304
#define NG   40
#define KK   49

typedef unsigned long long ull;

// f32x2 packed-math macros (sm_103a FFMA2 path)
#define FMA2(d,a,b,c) asm("fma.rn.f32x2 %0, %1, %2, %3;" : "=l"(d) : "l"(a), "l"(b), "l"(c))
#define MUL2(d,a,b)   asm("mul.rn.f32x2 %0, %1, %2;"     : "=l"(d) : "l"(a), "l"(b))
#define ADD2(d,a,b)   asm("add.rn.f32x2 %0, %1, %2;"     : "=l"(d) : "l"(a), "l"(b))
#define PK2(d,lo,hi)  asm("mov.b64 %0, {%1, %2};"        : "=l"(d) : "f"(lo), "f"(hi))
#define UPK2(lo,hi,s) asm("mov.b64 {%0, %1}, %2;"        : "=f"(lo), "=f"(hi) : "l"(s))

// Scratch (device globals, zero-initialized at load; padding never written)
__device__ float g_z[Bn * Cn];                                  // GAP [B,C]
__device__ float g_fs[Bn * HWn];                                // channel sum
__device__ float g_basis[NG * KK];                              // bases
__device__ __align__(16) float g_coeffT[3 * Bn * Cn * 16];      // [br,b,c,16n] padded
__device__ float g_G[3 * Bn * 256];                             // Gram/C, n*16+m padded
__device__ float g_s1[3 * Bn * 16];                             // colmean/C padded
__device__ __align__(16) float g_UP[(size_t)Bn * 3 * 16 * HWn]; // [b,br,16n,HW] padded

// ---------------------------------------------------------------------------
// k_prep: block 0 computes the 40 basis kernels; blocks 1..144 zero g_fs
__global__ void k_prep(const float* __restrict__ rw1, const float* __restrict__ rb1,
                       const float* __restrict__ rw2, const float* __restrict__ rb2) {
    int tid = threadIdx.x;
    if (blockIdx.x > 0) {
        int i = (blockIdx.x - 1) * 256 + tid;   // 144*256 = Bn*HWn
        g_fs[i] = 0.f;
        return;
    }
    __shared__ float r[KK], th[KK];
    if (tid < KK) {
        int i = tid / 7, j = tid % 7;
        float gy = (float)i - 3.f, gx = (float)j - 3.f;
        r[tid] = sqrtf(gx * gx + gy * gy + 1e-8f);
        th[tid] = atan2f(gy, gx);
    }
    __syncthreads();

    if (tid < 24) {
        bool inv = tid < 8;
        int i = inv ? tid : (tid - 8);
        int combo = i % 9;
        int d = combo / 3, si = combo % 3;
        float sig = inv ? (4.f + 2.f * (float)si) : (1.f + (float)si);
        float psi[KK];
        float ss = 0.f;
        for (int c = 0; c < KK; ++c) {
            float u = r[c] / sig;
            float g = expf(-0.5f * u * u);
            float p = (d == 0) ? 1.f : ((d == 1) ? u : (u * u - 1.f));
            psi[c] = p * g;
            ss += psi[c] * psi[c];
        }
        float inorm = 1.f / sqrtf(ss + 1e-8f);
        int gi = inv ? tid : (8 + i);
        for (int c = 0; c < KK; ++c) g_basis[gi * KK + c] = psi[c] * inorm;
    }

    if (tid < KK) {
        float rad0 = rb2[0], rad1 = rb2[1];
        for (int h = 0; h < 32; ++h) {
            float t = tanhf(r[tid] * rw1[h] + rb1[h]);
            rad0 += t * rw2[h * 2 + 0];
            rad1 += t * rw2[h * 2 + 1];
        }
        for (int l = 0; l < 8; ++l) {
            float o = (float)(l / 2 + 1);
            float a = (l & 1) ? sinf(o * th[tid]) : cosf(o * th[tid]);
            g_basis[(24 + l) * KK + tid]     = rad0 * a;
            g_basis[(24 + 8 + l) * KK + tid] = rad1 * a;
        }
    }
}

// ---------------------------------------------------------------------------
// k_reduce: round-0 champion verbatim. grid (16, B), block 256.
__global__ void k_reduce(const float* __restrict__ feat) {
    int b = blockIdx.y, chunk = blockIdx.x;
    int tid = threadIdx.x;
    int lane = tid & 31, wid = tid >> 5;
    __shared__ float zsum[16][8];

    float facc[9];
#pragma unroll
    for (int k = 0; k < 9; ++k) facc[k] = 0.f;

    const float* fb = feat + ((size_t)b * Cn + (size_t)chunk * 16) * HWn;
    for (int c = 0; c < 16; ++c) {
        const float* fp = fb + (size_t)c * HWn;
        float csum = 0.f;
#pragma unroll
        for (int k = 0; k < 9; ++k) {
            float v = fp[tid + 256 * k];
            facc[k] += v;
            csum += v;
        }
#pragma unroll
        for (int o = 16; o; o >>= 1) csum += __shfl_xor_sync(0xffffffffu, csum, o);
        if (lane == 0) zsum[c][wid] = csum;
    }
    __syncthreads();
    if (tid < 16) {
        float s = 0.f;
#pragma unroll
        for (int w = 0; w < 8; ++w) s += zsum[tid][w];
        g_z[b * Cn + chunk * 16 + tid] = s * (1.f / (float)HWn);
    }
#pragma unroll
    for (int k = 0; k < 9; ++k)
        atomicAdd(&g_fs[b * HWn + tid + 256 * k], facc[k]);
}

// ---------------------------------------------------------------------------
// k_mix: blockIdx-split fused kernel. Blocks 0..47 run the MLP (br,b);
// blocks 48..687 run uconv (g,b). Block 288 threads. Shared smem buffer.
#define SBUF_FLOATS 4672

template <int N>
__device__ __forceinline__ void mlp_body(
    int br, int b, int tid,
    const float* __restrict__ w1, const float* __restrict__ b1,
    const float* __restrict__ w2, const float* __restrict__ b2,
    float* sbuf) {
    float* zz = sbuf;            // 256
    float* hp = sbuf + 256;      // 4*64
    float* hh = sbuf + 512;      // 64
    float* sc = sbuf + 576;      // 16*256
    const int NC = N * Cn;
    if (tid < Cn) zz[tid] = g_z[b * Cn + tid];
    __syncthreads();
    if (tid < 256) {
        int j = tid & 63, s = tid >> 6;
        float a = 0.f;
        const float* wp = w1 + (size_t)(64 * s) * 64 + j;
#pragma unroll 8
        for (int c = 0; c < 64; ++c) a += zz[64 * s + c] * wp[c * 64];
        hp[s * 64 + j] = a;
    }
    __syncthreads();
    if (tid < 64)
        hh[tid] = fmaxf(hp[tid] + hp[64 + tid] + hp[128 + tid] + hp[192 + tid] + b1[tid], 0.f);
    __syncthreads();
    if (tid < Cn) {
        int c = tid;
        float acc[N];
#pragma unroll
        for (int n = 0; n < N; ++n) acc[n] = b2[n * Cn + c];
        for (int h2 = 0; h2 < 64; ++h2) {
            float hv = hh[h2];
            const float* wp = w2 + (size_t)h2 * NC + c;
#pragma unroll
            for (int n = 0; n < N; ++n) acc[n] += hv * wp[n * Cn];
        }
#pragma unroll
        for (int n = 0; n < N; ++n) sc[n * Cn + c] = acc[n];
        // transposed, padded coeff store: [c][16] (pad stays zero)
        float4* dst = (float4*)(g_coeffT + ((size_t)(br * Bn + b) * Cn + c) * 16);
#pragma unroll
        for (int k = 0; k < N / 4; ++k)
            dst[k] = make_float4(acc[4 * k], acc[4 * k + 1], acc[4 * k + 2], acc[4 * k + 3]);
    }
    __syncthreads();
    if (tid < N * N) {
        int n = tid / N, m = tid % N;
        float a = 0.f;
#pragma unroll 4
        for (int c = 0; c < Cn; ++c) a += sc[n * Cn + c] * sc[m * Cn + c];
        g_G[(br * Bn + b) * 256 + n * 16 + m] = a * (1.f / (float)Cn);  // n*16+m padded
    } else if (tid < N * N + N) {
        int n = tid - N * N;
        float a = 0.f;
#pragma unroll 4
        for (int c = 0; c < Cn; ++c) a += sc[n * Cn + c];
        g_s1[(br * Bn + b) * 16 + n] = a * (1.f / (float)Cn);
    }
}

__global__ void __launch_bounds__(288)
k_mix(const float* __restrict__ w1i, const float* __restrict__ b1i,
      const float* __restrict__ w2i, const float* __restrict__ b2i,
      const float* __restrict__ w1e, const float* __restrict__ b1e,
      const float* __restrict__ w2e, const float* __restrict__ b2e,
      const float* __restrict__ w1c, const float* __restrict__ b1c,
      const float* __restrict__ w2c, const float* __restrict__ b2c) {
    __shared__ float sbuf[SBUF_FLOATS];
    int bx = blockIdx.x, tid = threadIdx.x;

    if (bx < 48) {
        int br = bx / 16, b = bx % 16;
        if (br == 0)      mlp_body<8>(0, b, tid, w1i, b1i, w2i, b2i, sbuf);
        else if (br == 1) mlp_body<16>(1, b, tid, w1e, b1e, w2e, b2e, sbuf);
        else              mlp_body<16>(2, b, tid, w1c, b1c, w2c, b2c, sbuf);
        return;
    }

    // ---- uconv role ----
    int gb = bx - 48;
    int g = gb % NG, b = gb / NG;
    int br = (g < 8) ? 0 : ((g < 24) ? 1 : 2);
    int nl = g - ((br == 0) ? 0 : ((br == 1) ? 8 : 24));
    float* fp = sbuf;            // 54*54 = 2916
    float* bs = sbuf + 2916;     // 49
    if (tid < KK) bs[tid] = g_basis[g * KK + tid];
    for (int i = tid; i < 54 * 54; i += 288) {
        int row = i / 54, col = i % 54;
        int y = row - 3, x = col - 3;
        fp[i] = (y >= 0 && y < Hn && x >= 0 && x < Wn) ? g_fs[b * HWn + y * Wn + x] : 0.f;
    }
    __syncthreads();

    int x = tid % 48, yg0 = tid / 48;   // yg0 in 0..5
    float* up = g_UP + (((size_t)b * 3 + br) * 16 + nl) * HWn;
#pragma unroll
    for (int it = 0; it < 2; ++it) {
        int y0 = (yg0 + 6 * it) * 4;    // 4 vertically adjacent outputs
        float a0 = 0.f, a1 = 0.f, a2 = 0.f, a3 = 0.f;
#pragma unroll
        for (int ri = 0; ri < 10; ++ri) {
            float t[7];
#pragma unroll
            for (int dx = 0; dx < 7; ++dx) t[dx] = fp[(y0 + ri) * 54 + x + dx];
#pragma unroll
            for (int o = 0; o < 4; ++o) {
                int dy = ri - o;
                if (dy >= 0 && dy < 7) {
                    float s = 0.f;
#pragma unroll
                    for (int dx = 0; dx < 7; ++dx) s += t[dx] * bs[dy * 7 + dx];
                    if (o == 0) a0 += s; else if (o == 1) a1 += s;
                    else if (o == 2) a2 += s; else a3 += s;
                }
            }
        }
        up[(y0 + 0) * Wn + x] = a0;
        up[(y0 + 1) * Wn + x] = a1;
        up[(y0 + 2) * Wn + x] = a2;
        up[(y0 + 3) * Wn + x] = a3;
    }
}

// ---------------------------------------------------------------------------
// k_main v2: grid (6, B, 3) = 576 blocks (~4/SM), block 192, 2 px/thread,
// 4 independent FFMA2 accumulators per channel (chain depth 16 -> 4).
__global__ void __launch_bounds__(192)
k_main(const float* __restrict__ lig, const float* __restrict__ lib,
       const float* __restrict__ leg, const float* __restrict__ leb,
       const float* __restrict__ lcg, const float* __restrict__ lcb,
       float* __restrict__ out) {
    int chunk = blockIdx.x, b = blockIdx.y, br = blockIdx.z;
    int tid = threadIdx.x;

    const float* lng = (br == 0) ? lig : ((br == 1) ? leg : lcg);
    const float* lnb = (br == 0) ? lib : ((br == 1) ? leb : lcb);

    __shared__ ull s_cf[256 * 16];       // dup-packed coeffs [c][n]  (32 KB)
    __shared__ ulonglong2 s_gb[256];     // (gamma2, beta2)           (4 KB)
    __shared__ ull s_G[256];             // dup-packed Gram           (2 KB)
    __shared__ ull s_m1[16];

    const float4* cf4 = (const float4*)(g_coeffT + (size_t)(br * Bn + b) * Cn * 16);
    for (int i = tid; i < 1024; i += 192) {
        float4 v = cf4[i];
        ull p0, p1, p2, p3;
        PK2(p0, v.x, v.x); PK2(p1, v.y, v.y); PK2(p2, v.z, v.z); PK2(p3, v.w, v.w);
        s_cf[4 * i + 0] = p0; s_cf[4 * i + 1] = p1;
        s_cf[4 * i + 2] = p2; s_cf[4 * i + 3] = p3;
    }
    for (int i = tid; i < 256; i += 192) {
        float A = lng[i], Bc = lnb[i];
        ull a2, b2; PK2(a2, A, A); PK2(b2, Bc, Bc);
        s_gb[i] = make_ulonglong2(a2, b2);
        float gg = g_G[(br * Bn + b) * 256 + i];
        ull g2; PK2(g2, gg, gg);
        s_G[i] = g2;
    }
    if (tid < 16) {
        float s = g_s1[(br * Bn + b) * 16 + tid];
        ull s2; PK2(s2, s, s);
        s_m1[tid] = s2;
    }
    __syncthreads();

    int p0 = chunk * 384 + tid * 2;
    const float* ub = g_UP + ((size_t)b * 3 + br) * 16 * HWn;
    ull u[16];
#pragma unroll
    for (int n = 0; n < 16; ++n) {
        float2 v = *(const float2*)(ub + (size_t)n * HWn + p0);
        PK2(u[n], v.x, v.y);
    }

    // LN stats: mean + E[x^2] via Gram quadratic form (padding rows are zero)
    ull m = 0ull, q = 0ull;
#pragma unroll
    for (int n = 0; n < 16; ++n) FMA2(m, s_m1[n], u[n], m);
#pragma unroll
    for (int n = 0; n < 16; ++n) {
        ull t = 0ull;
#pragma unroll
        for (int mm = 0; mm < 16; ++mm) FMA2(t, s_G[n * 16 + mm], u[mm], t);
        FMA2(q, t, u[n], q);
    }
    float mx, my, qx, qy;
    UPK2(mx, my, m); UPK2(qx, qy, q);
    float rx = rsqrtf(fmaxf(qx - mx * mx, 0.f) + 1e-5f);
    float ry = rsqrtf(fmaxf(qy - my * my, 0.f) + 1e-5f);
    ull r2, nm;
    PK2(r2, rx, ry);
    PK2(nm, -mx, -my);

    float* ob = out + (size_t)br * Bn * Cn * HWn + (size_t)b * Cn * HWn + p0;
#pragma unroll 4
    for (int c = 0; c < 256; ++c) {
        // 4 independent accumulator chains (depth 4 each), tree combine
        ull v0 = 0ull, v1 = 0ull, v2 = 0ull, v3 = 0ull;
        const ulonglong2* w2 = (const ulonglong2*)(s_cf + c * 16);
        ulonglong2 wa = w2[0], wb = w2[1], wc = w2[2], wd = w2[3];
        FMA2(v0, wa.x, u[0],  v0); FMA2(v1, wa.y, u[1],  v1);
        FMA2(v2, wb.x, u[2],  v2); FMA2(v3, wb.y, u[3],  v3);
        FMA2(v0, wc.x, u[4],  v0); FMA2(v1, wc.y, u[5],  v1);
        FMA2(v2, wd.x, u[6],  v2); FMA2(v3, wd.y, u[7],  v3);
        wa = w2[4]; wb = w2[5]; wc = w2[6]; wd = w2[7];
        FMA2(v0, wa.x, u[8],  v0); FMA2(v1, wa.y, u[9],  v1);
        FMA2(v2, wb.x, u[10], v2); FMA2(v3, wb.y, u[11], v3);
        FMA2(v0, wc.x, u[12], v0); FMA2(v1, wc.y, u[13], v1);
        FMA2(v2, wd.x, u[14], v2); FMA2(v3, wd.y, u[15], v3);
        ull va, vb, v;
        ADD2(va, v0, v1); ADD2(vb, v2, v3); ADD2(v, va, vb);

        ulonglong2 gb = s_gb[c];
        ull rA, bias, o;
        MUL2(rA, r2, gb.x);
        FMA2(bias, nm, rA, gb.y);
        FMA2(o, v, rA, bias);
        *(ull*)(ob + (size_t)c * HWn) = o;
    }
}

// ---------------------------------------------------------------------------
extern "C" void kernel_launch(void* const* d_in, const int* in_sizes, int n_in,
                              void* d_out, int out_size) {
    const float* feat = (const float*)d_in[0];
    const float* iw1 = (const float*)d_in[1];
    const float* ib1 = (const float*)d_in[2];
    const float* iw2 = (const float*)d_in[3];
    const float* ib2 = (const float*)d_in[4];
    const float* ew1 = (const float*)d_in[5];
    const float* eb1 = (const float*)d_in[6];
    const float* ew2 = (const float*)d_in[7];
    const float* eb2 = (const float*)d_in[8];
    const float* cw1 = (const float*)d_in[9];
    const float* cb1 = (const float*)d_in[10];
    const float* cw2 = (const float*)d_in[11];
    const float* cb2 = (const float*)d_in[12];
    const float* rw1 = (const float*)d_in[13];
    const float* rb1 = (const float*)d_in[14];
    const float* rw2 = (const float*)d_in[15];
    const float* rb2 = (const float*)d_in[16];
    const float* lig = (const float*)d_in[17];
    const float* lib = (const float*)d_in[18];
    const float* leg = (const float*)d_in[19];
    const float* leb = (const float*)d_in[20];
    const float* lcg = (const float*)d_in[21];
    const float* lcb = (const float*)d_in[22];
    float* out = (float*)d_out;

    k_prep<<<145, 256>>>(rw1, rb1, rw2, rb2);
    k_reduce<<<dim3(16, Bn), 256>>>(feat);
    k_mix<<<688, 288>>>(iw1, ib1, iw2, ib2, ew1, eb1, ew2, eb2, cw1, cb1, cw2, cb2);
    k_main<<<dim3(6, Bn, 3), 192>>>(lig, lib, leg, leb, lcg, lcb, out);
}